// round 13
// baseline (speedup 1.0000x reference)
#include <cuda_runtime.h>
#include <cstdint>

#define NTIME 2000
#define NBATCH 128
#define INSIZE 256
#define OSIZE 40
#define NTRANS 32
#define NROWS (NTIME * NBATCH)
#define CHUNK 10
#define NCHUNK (NTIME / CHUNK)   // 200
#define GRP 10
#define NGRP (NCHUNK / GRP)      // 20

// exp(trans), TRANSPOSED layout: (t, b, ch) at [(t*32+ch)*128 + b].
// +8 timesteps pad so k2a's prefetch can read past the end.
__device__ float g_ew[(NTIME + 8) * NBATCH * NTRANS];
// Normalized per-chunk 8x8 matrices, coalesced: float4 idx (c*16+q)*128 + b.
__device__ float g_chunkM[NCHUNK * NBATCH * 64];
__device__ int   g_chunkE[NCHUNK * NBATCH];     // power-of-2 exponents
// Group matrices (products of 10 chunks), +1 group pad.
__device__ float g_grpM[(NGRP + 1) * NBATCH * 64];
__device__ int   g_grpE[NGRP * NBATCH];
__device__ float g_logZ[NBATCH];   // already divided by NTIME

// ---------------- f32x2 packed helpers (Blackwell) ----------------
__device__ __forceinline__ unsigned long long pack2(float lo, float hi) {
    unsigned long long r;
    asm("mov.b64 %0, {%1, %2};" : "=l"(r) : "f"(lo), "f"(hi));
    return r;
}
__device__ __forceinline__ void unpack2(unsigned long long v, float& lo, float& hi) {
    asm("mov.b64 {%0, %1}, %2;" : "=f"(lo), "=f"(hi) : "l"(v));
}
__device__ __forceinline__ unsigned long long fma2(unsigned long long a,
                                                   unsigned long long b,
                                                   unsigned long long c) {
    unsigned long long d;
    asm("fma.rn.f32x2 %0, %1, %2, %3;" : "=l"(d) : "l"(a), "l"(b), "l"(c));
    return d;
}
__device__ __forceinline__ unsigned long long add2(unsigned long long a,
                                                   unsigned long long b) {
    unsigned long long d;
    asm("add.rn.f32x2 %0, %1, %2;" : "=l"(d) : "l"(a), "l"(b));
    return d;
}
__device__ __forceinline__ unsigned long long mul2(unsigned long long a,
                                                   unsigned long long b) {
    unsigned long long d;
    asm("mul.rn.f32x2 %0, %1, %2;" : "=l"(d) : "l"(a), "l"(b));
    return d;
}

__device__ __forceinline__ float softplus_f(float v) {
    // matches jax.nn.softplus = max(v,0) + log1p(exp(-|v|))
    return fmaxf(v, 0.0f) + log1pf(expf(-fabsf(v)));
}

// ---------------- Kernel 1: GEMM, fully-coalesced I/O -----------------------
// Dynamic smem: wp (40KB weight pairs) + xs[32][257] (x staging, reused as the
// out-staging buffer in the epilogue) + bias.
// half = tid>>7 picks 20 output channels (warp-uniform -> broadcast LDS.128);
// lrow = tid&127: rows (blk*256+lrow, +128). Warp lanes = consecutive batch b,
// so transposed ew stores are 1-line coalesced STG.32. out rows are staged in
// smem (stride 41 -> conflict-free STS) and written as coalesced STG.128.
// launch_bounds(256,2): 128-reg budget -> NO SPILLS (the (256,3)=85-reg cap
// was forcing local-memory spills of the 40-reg accumulator file).
#define XS_STRIDE 257
#define ST_STRIDE 41
__global__ void __launch_bounds__(256, 2) k1_gemm_act(
    const float* __restrict__ x, const float* __restrict__ W,
    const float* __restrict__ bias, float* __restrict__ out)
{
    extern __shared__ __align__(16) unsigned char smraw[];
    unsigned long long* wp = (unsigned long long*)smraw;          // [INSIZE*20]
    float* xs = (float*)(smraw + INSIZE * 20 * 8);                // [32][257]
    float* bs = xs + 32 * XS_STRIDE;                              // [40]
    float* stage = xs;             // epilogue alias: [128][ST_STRIDE] = 21KB

    int tid = threadIdx.x;
    for (int idx = tid; idx < INSIZE * 20; idx += 256) {
        int k = idx / 20, p = idx % 20;
        wp[idx] = pack2(W[(2 * p) * INSIZE + k], W[(2 * p + 1) * INSIZE + k]);
    }
    if (tid < OSIZE) bs[tid] = bias[tid];
    __syncthreads();

    int half = tid >> 7;            // 0: channels 0..19, 1: channels 20..39
    int lrow = tid & 127;
    int rowA = blockIdx.x * 256 + lrow;

    unsigned long long acc[2][10];
#pragma unroll
    for (int p = 0; p < 10; p++) {
        int g = half * 20 + 2 * p;
        unsigned long long bv = pack2(bs[g], bs[g + 1]);
        acc[0][p] = bv;
        acc[1][p] = bv;
    }

    const float4* x4 = (const float4*)x;
    int f4 = tid & 7;               // float4 slot within 32-k tile (8 per row)
    int r0 = tid >> 3;              // staging row base (32 rows per pass)

    for (int kc = 0; kc < INSIZE; kc += 32) {
        if (kc) __syncthreads();    // xs reuse barrier
        // ---- stage 256 rows x 32 k, coalesced (4 lines per warp LDG) ----
#pragma unroll
        for (int rr = 0; rr < 8; rr++) {
            int row = (rr << 5) + r0;
            float4 v = __ldcg(&x4[(size_t)(blockIdx.x * 256 + row) * (INSIZE / 4)
                                  + (kc >> 2) + f4]);
            xs[(f4 * 4 + 0) * XS_STRIDE + row] = v.x;
            xs[(f4 * 4 + 1) * XS_STRIDE + row] = v.y;
            xs[(f4 * 4 + 2) * XS_STRIDE + row] = v.z;
            xs[(f4 * 4 + 3) * XS_STRIDE + row] = v.w;
        }
        __syncthreads();
        // ---- compute 32 k ----
#pragma unroll 4
        for (int kk = 0; kk < 32; kk++) {
            float xa = xs[kk * XS_STRIDE + lrow];          // conflict-free LDS.32
            float xb = xs[kk * XS_STRIDE + lrow + 128];
            unsigned long long xxa = pack2(xa, xa);
            unsigned long long xxb = pack2(xb, xb);
            const ulonglong2* wr = (const ulonglong2*)(wp + (kc + kk) * 20 + half * 10);
#pragma unroll
            for (int j = 0; j < 5; j++) {
                ulonglong2 wv = wr[j];            // broadcast LDS.128 -> 4 fma2
                acc[0][2 * j]     = fma2(xxa, wv.x, acc[0][2 * j]);
                acc[0][2 * j + 1] = fma2(xxa, wv.y, acc[0][2 * j + 1]);
                acc[1][2 * j]     = fma2(xxb, wv.x, acc[1][2 * j]);
                acc[1][2 * j + 1] = fma2(xxb, wv.y, acc[1][2 * j + 1]);
            }
        }
    }

    // ---------------- epilogue: two 128-row panels ----------------
#pragma unroll 1
    for (int r = 0; r < 2; r++) {
        int row = rowA + r * 128;
        int t = row >> 7;
        int b = row & 127;
        float y[20];
#pragma unroll
        for (int p = 0; p < 10; p++) unpack2(acc[r][p], y[2 * p], y[2 * p + 1]);

        float o[20];
        float* ewb = g_ew + (size_t)t * NTRANS * NBATCH + b;   // + tc*128

        if (half == 0) {
#pragma unroll
            for (int c = 0; c < 4; c++) o[c] = 1.0f + softplus_f(y[c]);
#pragma unroll
            for (int c = 4; c < 8; c++) o[c] = 0.1f + softplus_f(y[c]);
#pragma unroll
            for (int c = 8; c < 20; c++) {                 // trans ch 0..11
                float tr = 5.0f * tanhf(y[c]);
                o[c] = tr;                                 // logZ fixed by k3
                ewb[(size_t)(c - 8) * NBATCH] = __expf(tr);  // coalesced STG.32
            }
        } else {
#pragma unroll
            for (int c = 0; c < 20; c++) {                 // trans ch 12..31
                float tr = 5.0f * tanhf(y[c]);
                o[c] = tr;
                ewb[(size_t)(c + 12) * NBATCH] = __expf(tr);
            }
        }

        __syncthreads();            // xs/stage free (or prev panel drained)
#pragma unroll
        for (int c = 0; c < 20; c++)
            stage[lrow * ST_STRIDE + half * 20 + c] = o[c];  // conflict-free STS
        __syncthreads();
        // coalesced readout: 1280 float4 = 256 threads x 5
        float* obase = out + (size_t)(blockIdx.x * 256 + r * 128) * OSIZE;
#pragma unroll
        for (int q = 0; q < 5; q++) {
            int g4 = q * 256 + tid;
            int g = 4 * g4;
            int rl = g / OSIZE;
            int ch = g - rl * OSIZE;
            const float* sp = stage + rl * ST_STRIDE + ch;
            float4 v = make_float4(sp[0], sp[1], sp[2], sp[3]);
            ((float4*)obase)[g4] = v;
        }
    }
}

#define K1_SMEM (INSIZE * 20 * 8 + 32 * XS_STRIDE * 4 + OSIZE * 4)

// ---------------- CRF step in exp domain ----------------
// Transposed layout: e[ch] at g_ew[(t*32+ch)*128 + b] -> coalesced LDG.32.
__device__ __forceinline__ void loadE(float e[NTRANS], int t, int b) {
    const float* p = g_ew + (size_t)t * NTRANS * NBATCH + b;
#pragma unroll
    for (int ch = 0; ch < NTRANS; ch++) e[ch] = p[(size_t)ch * NBATCH];
}

__device__ __forceinline__ void stepf(float p[8], const float e[NTRANS]) {
    float np[8];
#pragma unroll
    for (int i = 0; i < 4; i++) {
        float m = 0.0f, s = 0.0f;
#pragma unroll
        for (int j = 0; j < 8; j++) {
            float v = p[j] * e[i * 8 + j];
            if (j == i || j == i + 4) s += v;   // "stay" terms
            else                      m += v;   // "move" terms
        }
        np[i] = m;
        np[i + 4] = s;
    }
#pragma unroll
    for (int i = 0; i < 8; i++) p[i] = np[i];
}

// ---------------- Kernel 2a: per-chunk matrices, normalized ----------------
__global__ void __launch_bounds__(128, 1) k2a_chunk()
{
    int b = threadIdx.x;           // batch
    int c = blockIdx.x;            // chunk
    int t0 = c * CHUNK;

    float M[8][8];                 // M[j] = column j
#pragma unroll
    for (int j = 0; j < 8; j++)
#pragma unroll
        for (int i = 0; i < 8; i++) M[j][i] = (i == j) ? 1.0f : 0.0f;

    float eA[NTRANS], eB[NTRANS];
    loadE(eA, t0, b);
#pragma unroll 1
    for (int s = 0; s < CHUNK; s += 2) {
        loadE(eB, t0 + s + 1, b);
#pragma unroll
        for (int j = 0; j < 8; j++) stepf(M[j], eA);
        loadE(eA, t0 + s + 2, b);   // s=8 reads pad: discarded
#pragma unroll
        for (int j = 0; j < 8; j++) stepf(M[j], eB);
    }

    // normalize by exact power of two (max entry -> [1,2))
    float maxv = 0.0f;
#pragma unroll
    for (int j = 0; j < 8; j++)
#pragma unroll
        for (int i = 0; i < 8; i++) maxv = fmaxf(maxv, M[j][i]);
    int e = (int)(__float_as_uint(maxv) >> 23) - 127;
    float scale = __uint_as_float((unsigned)(127 - e) << 23);
#pragma unroll
    for (int j = 0; j < 8; j++)
#pragma unroll
        for (int i = 0; i < 8; i++) M[j][i] *= scale;
    g_chunkE[c * NBATCH + b] = e;

    float4* dst = (float4*)g_chunkM;
#pragma unroll
    for (int j = 0; j < 8; j++) {
        dst[((size_t)c * 16 + 2 * j)     * NBATCH + b] = make_float4(M[j][0], M[j][1], M[j][2], M[j][3]);
        dst[((size_t)c * 16 + 2 * j + 1) * NBATCH + b] = make_float4(M[j][4], M[j][5], M[j][6], M[j][7]);
    }
}

// load matrix as u64 column-pairs: m[4*j+qq] = (M[j][2qq], M[j][2qq+1])
__device__ __forceinline__ void loadMp(unsigned long long m[32],
                                       const float* srcM, int c, int b) {
    const float4* p4 = (const float4*)srcM;
#pragma unroll
    for (int q = 0; q < 16; q++) {
        float4 t = p4[((size_t)c * 16 + q) * NBATCH + b];   // coalesced
        m[2 * q]     = pack2(t.x, t.y);
        m[2 * q + 1] = pack2(t.z, t.w);
    }
}

// ---------------- Kernel 2b: group products of 10 chunk matrices ------------
// grid 20 x 128. G <- M_{10g+9}...M_{10g}. Normalized-chunk entries <= 2 ->
// product entries <= 8^9 * 2^10 = 2^37: no overflow, no renorm needed.
__global__ void __launch_bounds__(128, 1) k2b_grp()
{
    int b = threadIdx.x;
    int g = blockIdx.x;

    float G[8][8];                  // G[j] = column j
    {
        const float4* p4 = (const float4*)g_chunkM;
#pragma unroll
        for (int q = 0; q < 16; q++) {
            float4 t = p4[((size_t)(g * GRP) * 16 + q) * NBATCH + b];
            int j = q >> 1, h = (q & 1) * 4;
            G[j][h] = t.x; G[j][h + 1] = t.y; G[j][h + 2] = t.z; G[j][h + 3] = t.w;
        }
    }

#pragma unroll 1
    for (int s = 1; s < GRP; s++) {
        unsigned long long A[32];
        loadMp(A, g_chunkM, g * GRP + s, b);
#pragma unroll
        for (int j = 0; j < 8; j++) {
            unsigned long long nv[4];
#pragma unroll
            for (int qq = 0; qq < 4; qq++) nv[qq] = pack2(0.0f, 0.0f);
#pragma unroll
            for (int jj = 0; jj < 8; jj++) {
                unsigned long long vj = pack2(G[j][jj], G[j][jj]);
#pragma unroll
                for (int qq = 0; qq < 4; qq++)
                    nv[qq] = fma2(A[4 * jj + qq], vj, nv[qq]);
            }
#pragma unroll
            for (int qq = 0; qq < 4; qq++)
                unpack2(nv[qq], G[j][2 * qq], G[j][2 * qq + 1]);
        }
    }

    int esum = 0;
#pragma unroll
    for (int s = 0; s < GRP; s++) esum += g_chunkE[(g * GRP + s) * NBATCH + b];
    g_grpE[g * NBATCH + b] = esum;

    float4* dst = (float4*)g_grpM;
#pragma unroll
    for (int j = 0; j < 8; j++) {
        dst[((size_t)g * 16 + 2 * j)     * NBATCH + b] = make_float4(G[j][0], G[j][1], G[j][2], G[j][3]);
        dst[((size_t)g * 16 + 2 * j + 1) * NBATCH + b] = make_float4(G[j][4], G[j][5], G[j][6], G[j][7]);
    }
}

// ---------------- Kernel 2c: two independent 10-deep folds (R11 version) ----
// logZ needs 1^T * (G_19 ... G_0) * 1. Split:
//   R = G_9 ... G_0 * 1        (column chain, ascending)
//   L = 1^T * G_19 ... G_10    (row chain, descending)
// Chains independent -> 2x ILP; final S = L . R.
// Renorm per fold via exact power-of-2 exponent extraction (no logf/div).
__device__ __forceinline__ void foldR(const unsigned long long m[32],
                                      float v[8], int& esum) {
    unsigned long long nv[4];
#pragma unroll
    for (int qq = 0; qq < 4; qq++) nv[qq] = pack2(0.0f, 0.0f);
#pragma unroll
    for (int j = 0; j < 8; j++) {
        unsigned long long vj = pack2(v[j], v[j]);
#pragma unroll
        for (int qq = 0; qq < 4; qq++)
            nv[qq] = fma2(m[4 * j + qq], vj, nv[qq]);
    }
    unsigned long long t = add2(add2(nv[0], nv[1]), add2(nv[2], nv[3]));
    float slo, shi;
    unpack2(t, slo, shi);
    float S = slo + shi;
    int e = (int)(__float_as_uint(S) >> 23) - 127;
    float scale = __uint_as_float((unsigned)(127 - e) << 23);   // exact 2^-e
    esum += e;
    unsigned long long s2 = pack2(scale, scale);
#pragma unroll
    for (int qq = 0; qq < 4; qq++) {
        unsigned long long u = mul2(nv[qq], s2);
        unpack2(u, v[2 * qq], v[2 * qq + 1]);
    }
}

__device__ __forceinline__ void foldL(const unsigned long long m[32],
                                      float u[8], int& esum) {
    // u_new[j] = dot(u, column j)
    unsigned long long up[4];
#pragma unroll
    for (int qq = 0; qq < 4; qq++) up[qq] = pack2(u[2 * qq], u[2 * qq + 1]);
    float nu[8];
#pragma unroll
    for (int j = 0; j < 8; j++) {
        unsigned long long d = mul2(m[4 * j], up[0]);
#pragma unroll
        for (int qq = 1; qq < 4; qq++)
            d = fma2(m[4 * j + qq], up[qq], d);
        float lo, hi;
        unpack2(d, lo, hi);
        nu[j] = lo + hi;
    }
    float S = ((nu[0] + nu[1]) + (nu[2] + nu[3])) + ((nu[4] + nu[5]) + (nu[6] + nu[7]));
    int e = (int)(__float_as_uint(S) >> 23) - 127;
    float scale = __uint_as_float((unsigned)(127 - e) << 23);
    esum += e;
#pragma unroll
    for (int j = 0; j < 8; j++) u[j] = nu[j] * scale;
}

__global__ void __launch_bounds__(32, 1) k2c_combine()
{
    int b = blockIdx.x * 32 + threadIdx.x;

    int esum = 0;
#pragma unroll
    for (int g = 0; g < NGRP; g++) esum += g_grpE[g * NBATCH + b];

    float v[8], u[8];
#pragma unroll
    for (int i = 0; i < 8; i++) { v[i] = 1.0f; u[i] = 1.0f; }

#pragma unroll 1
    for (int s = 0; s < NGRP / 2; s++) {
        unsigned long long mV[32], mU[32];
        loadMp(mV, g_grpM, s, b);               // R chain: G_0 .. G_9
        loadMp(mU, g_grpM, NGRP - 1 - s, b);    // L chain: G_19 .. G_10
        foldR(mV, v, esum);
        foldL(mU, u, esum);
    }

    float S = 0.0f;
#pragma unroll
    for (int i = 0; i < 8; i++) S = fmaf(u[i], v[i], S);
    double lz = ((double)esum * 0.69314718055994530942 + log((double)S))
                / (double)NTIME;
    g_logZ[b] = (float)lz;
}

// ---------------- Kernel 3: out[..., 8:40] -= logZ[b] ----------------
__global__ void __launch_bounds__(256) k3_fixup(float* __restrict__ out)
{
    int q = blockIdx.x * 256 + threadIdx.x;      // one float4 of 32 trans channels
    if (q >= NTIME * NBATCH * 8) return;
    int tb = q >> 3;
    int sub = q & 7;
    float lz = g_logZ[tb & (NBATCH - 1)];
    float4* ptr = (float4*)(out + (size_t)tb * OSIZE + 8) + sub;
    float4 v = *ptr;
    v.x -= lz; v.y -= lz; v.z -= lz; v.w -= lz;
    *ptr = v;
}

extern "C" void kernel_launch(void* const* d_in, const int* in_sizes, int n_in,
                              void* d_out, int out_size)
{
    const float* x = (const float*)d_in[0];
    const float* W = (const float*)d_in[1];
    const float* b = (const float*)d_in[2];
    float* out = (float*)d_out;

    static int smem_set = 0;
    if (!smem_set) {
        cudaFuncSetAttribute(k1_gemm_act,
                             cudaFuncAttributeMaxDynamicSharedMemorySize, K1_SMEM);
        smem_set = 1;
    }

    k1_gemm_act<<<NROWS / 256, 256, K1_SMEM>>>(x, W, b, out);
    k2a_chunk<<<NCHUNK, 128>>>();
    k2b_grp<<<NGRP, 128>>>();
    k2c_combine<<<NBATCH / 32, 32>>>();
    k3_fixup<<<(NTIME * NBATCH * 8 + 255) / 256, 256>>>(out);
}

// round 16
// speedup vs baseline: 1.4863x; 1.4863x over previous
#include <cuda_runtime.h>
#include <cuda_bf16.h>
#include <cstdint>

#define NTIME 2000
#define NBATCH 128
#define INSIZE 256
#define OSIZE 40
#define NTRANS 32
#define NROWS (NTIME * NBATCH)
#define CHUNK 10
#define NCHUNK (NTIME / CHUNK)   // 200
#define GRP 10
#define NGRP (NCHUNK / GRP)      // 20

// exp(trans), TRANSPOSED layout: (t, b, ch) at [(t*32+ch)*128 + b].
// +8 timesteps pad so k2a's prefetch can read past the end.
__device__ float g_ew[(NTIME + 8) * NBATCH * NTRANS];
// Normalized per-chunk 8x8 matrices, coalesced: float4 idx (c*16+q)*128 + b.
__device__ float g_chunkM[NCHUNK * NBATCH * 64];
__device__ int   g_chunkE[NCHUNK * NBATCH];     // power-of-2 exponents
// Group matrices (products of 10 chunks), +1 group pad.
__device__ float g_grpM[(NGRP + 1) * NBATCH * 64];
__device__ int   g_grpE[NGRP * NBATCH];
__device__ float g_logZ[NBATCH];   // already divided by NTIME

// ---------------- f32x2 packed helpers (Blackwell) ----------------
__device__ __forceinline__ unsigned long long pack2(float lo, float hi) {
    unsigned long long r;
    asm("mov.b64 %0, {%1, %2};" : "=l"(r) : "f"(lo), "f"(hi));
    return r;
}
__device__ __forceinline__ void unpack2(unsigned long long v, float& lo, float& hi) {
    asm("mov.b64 {%0, %1}, %2;" : "=f"(lo), "=f"(hi) : "l"(v));
}
__device__ __forceinline__ unsigned long long fma2(unsigned long long a,
                                                   unsigned long long b,
                                                   unsigned long long c) {
    unsigned long long d;
    asm("fma.rn.f32x2 %0, %1, %2, %3;" : "=l"(d) : "l"(a), "l"(b), "l"(c));
    return d;
}
__device__ __forceinline__ unsigned long long add2(unsigned long long a,
                                                   unsigned long long b) {
    unsigned long long d;
    asm("add.rn.f32x2 %0, %1, %2;" : "=l"(d) : "l"(a), "l"(b));
    return d;
}
__device__ __forceinline__ unsigned long long mul2(unsigned long long a,
                                                   unsigned long long b) {
    unsigned long long d;
    asm("mul.rn.f32x2 %0, %1, %2;" : "=l"(d) : "l"(a), "l"(b));
    return d;
}

__device__ __forceinline__ float softplus_f(float v) {
    // matches jax.nn.softplus = max(v,0) + log1p(exp(-|v|))
    return fmaxf(v, 0.0f) + log1pf(expf(-fabsf(v)));
}

__device__ __forceinline__ uint32_t smem_u32(const void* p) {
    uint32_t a;
    asm("{ .reg .u64 t; cvta.to.shared.u64 t, %1; cvt.u32.u64 %0, t; }"
        : "=r"(a) : "l"(p));
    return a;
}

// ---------------- mma.sync helpers (portable sm_80+ path) ----------------
__device__ __forceinline__ void ldm_x4(uint32_t& r0, uint32_t& r1,
                                       uint32_t& r2, uint32_t& r3, uint32_t addr) {
    asm volatile("ldmatrix.sync.aligned.m8n8.x4.shared.b16 {%0,%1,%2,%3}, [%4];"
                 : "=r"(r0), "=r"(r1), "=r"(r2), "=r"(r3) : "r"(addr));
}
__device__ __forceinline__ void ldm_x2(uint32_t& r0, uint32_t& r1, uint32_t addr) {
    asm volatile("ldmatrix.sync.aligned.m8n8.x2.shared.b16 {%0,%1}, [%2];"
                 : "=r"(r0), "=r"(r1) : "r"(addr));
}
__device__ __forceinline__ void mma_bf16(float* d, const uint32_t* a,
                                         const uint32_t* b) {
    asm volatile(
        "mma.sync.aligned.m16n8k16.row.col.f32.bf16.bf16.f32 "
        "{%0,%1,%2,%3}, {%4,%5,%6,%7}, {%8,%9}, {%0,%1,%2,%3};"
        : "+f"(d[0]), "+f"(d[1]), "+f"(d[2]), "+f"(d[3])
        : "r"(a[0]), "r"(a[1]), "r"(a[2]), "r"(a[3]), "r"(b[0]), "r"(b[1]));
}

// ---------------- Kernel 1: split-bf16 mma.sync GEMM + activations ----------
// One CTA = one timestep t (128 batch rows), 4 warps; warp w owns rows
// [w*32, w*32+32) (2 m16 tiles) x all 40 cols (5 n8 tiles), K=256.
// y = Ah*Bh + Ah*Bl + Al*Bh, fp32 accumulators (dropped Al*Bl <= 2^-18/term).
// SMEM: bias | B_hi | B_lo (40x264 bf16, 528B stride: ldmatrix conflict-free)
//       | A_hi | A_lo (128x72 bf16, 144B stride, 64-k chunk staging).
#define A_STRIDE_B 144               // bytes per A row (72 bf16)
#define B_STRIDE_B 528               // bytes per B row (264 bf16)
#define SM_BIAS 0
#define SM_BH   1024
#define SM_BL   (SM_BH + 21504)      // 40*528 = 21120, rounded
#define SM_AH   (SM_BL + 21504)
#define SM_AL   (SM_AH + 18432)     // 128*144
#define K1_SMEM (SM_AL + 18432)     // 80896 B

__global__ void __launch_bounds__(128, 2)
k1_gemm_mma(const float* __restrict__ x, const float* __restrict__ W,
            const float* __restrict__ bias, float* __restrict__ out)
{
    extern __shared__ __align__(1024) unsigned char smem[];
    uint32_t smb = smem_u32(smem);
    int tid = threadIdx.x;
    int w = tid >> 5;
    int lane = tid & 31;

    if (tid < OSIZE) ((float*)(smem + SM_BIAS))[tid] = bias[tid];

    // ---- stage B = W as bf16 hi/lo, layout [n][k] (row n contiguous in k) ----
    for (int idx = tid; idx < OSIZE * 128; idx += 128) {
        int n = idx >> 7;
        int q = idx & 127;           // k pair index, k = 2q
        float2 wv = ((const float2*)W)[(size_t)n * 128 + q];
        float h0 = (float)__float2bfloat16(wv.x);
        float h1 = (float)__float2bfloat16(wv.y);
        uint32_t hp, lp;
        asm("cvt.rn.bf16x2.f32 %0, %1, %2;" : "=r"(hp) : "f"(h1), "f"(h0));
        asm("cvt.rn.bf16x2.f32 %0, %1, %2;" : "=r"(lp) : "f"(wv.y - h1), "f"(wv.x - h0));
        uint32_t off = (uint32_t)n * B_STRIDE_B + (uint32_t)q * 4;
        *(uint32_t*)(smem + SM_BH + off) = hp;
        *(uint32_t*)(smem + SM_BL + off) = lp;
    }

    float acc[2][5][4];
#pragma unroll
    for (int mt = 0; mt < 2; mt++)
#pragma unroll
        for (int nt = 0; nt < 5; nt++)
#pragma unroll
            for (int e = 0; e < 4; e++) acc[mt][nt][e] = 0.0f;

    const float4* x4 = (const float4*)x + (size_t)blockIdx.x * 128 * 64;
    int f4 = tid & 15;              // float4 slot within 64-k chunk
    int r0 = tid >> 4;              // 8 row-groups

    // ldmatrix address components (per thread, constant across loop)
    int aRow0 = w * 32 + ((lane >> 3) & 1) * 8 + (lane & 7);  // + mt*16
    int aKoff = (lane >> 4) * 16;                             // + ks*32
    int l16 = lane & 15;
    int bN = (l16 & 7);                                       // + nt*8
    int bKoff = (l16 >> 3) * 16;                              // + kglob*2

#pragma unroll 1
    for (int c = 0; c < 4; c++) {
        __syncthreads();            // A smem reuse barrier
        // ---- stage A chunk: 128 rows x 64 k, coalesced LDG -> bf16 hi/lo ----
#pragma unroll
        for (int rr = 0; rr < 16; rr++) {
            int row = rr * 8 + r0;
            float4 v = __ldcg(&x4[(size_t)row * 64 + c * 16 + f4]);
            float h0 = (float)__float2bfloat16(v.x);
            float h1 = (float)__float2bfloat16(v.y);
            float h2 = (float)__float2bfloat16(v.z);
            float h3 = (float)__float2bfloat16(v.w);
            uint32_t hp0, hp1, lp0, lp1;
            asm("cvt.rn.bf16x2.f32 %0, %1, %2;" : "=r"(hp0) : "f"(h1), "f"(h0));
            asm("cvt.rn.bf16x2.f32 %0, %1, %2;" : "=r"(hp1) : "f"(h3), "f"(h2));
            asm("cvt.rn.bf16x2.f32 %0, %1, %2;" : "=r"(lp0) : "f"(v.y - h1), "f"(v.x - h0));
            asm("cvt.rn.bf16x2.f32 %0, %1, %2;" : "=r"(lp1) : "f"(v.w - h3), "f"(v.z - h2));
            uint32_t off = (uint32_t)row * A_STRIDE_B + (uint32_t)f4 * 8;
            *(unsigned long long*)(smem + SM_AH + off) =
                ((unsigned long long)hp1 << 32) | hp0;
            *(unsigned long long*)(smem + SM_AL + off) =
                ((unsigned long long)lp1 << 32) | lp0;
        }
        __syncthreads();
        // ---- compute: 4 k16 steps ----
#pragma unroll
        for (int ks = 0; ks < 4; ks++) {
            uint32_t ah[2][4], al[2][4];
#pragma unroll
            for (int mt = 0; mt < 2; mt++) {
                uint32_t aoff = (uint32_t)(aRow0 + mt * 16) * A_STRIDE_B
                                + (uint32_t)(ks * 32 + aKoff);
                ldm_x4(ah[mt][0], ah[mt][1], ah[mt][2], ah[mt][3],
                       smb + SM_AH + aoff);
                ldm_x4(al[mt][0], al[mt][1], al[mt][2], al[mt][3],
                       smb + SM_AL + aoff);
            }
            int kglob = c * 64 + ks * 16;
#pragma unroll
            for (int nt = 0; nt < 5; nt++) {
                uint32_t boff = (uint32_t)(nt * 8 + bN) * B_STRIDE_B
                                + (uint32_t)(kglob * 2 + bKoff);
                uint32_t bh[2], bl[2];
                ldm_x2(bh[0], bh[1], smb + SM_BH + boff);
                ldm_x2(bl[0], bl[1], smb + SM_BL + boff);
#pragma unroll
                for (int mt = 0; mt < 2; mt++) {
                    mma_bf16(acc[mt][nt], ah[mt], bh);
                    mma_bf16(acc[mt][nt], ah[mt], bl);
                    mma_bf16(acc[mt][nt], al[mt], bh);
                }
            }
        }
    }

    // ---- epilogue: fragments -> smem y stage [128][41] ----
    __syncthreads();
    float* ystage = (float*)(smem + SM_AH);     // 128*41*4 = 20992 <= 36864
#pragma unroll
    for (int mt = 0; mt < 2; mt++) {
        int r = w * 32 + mt * 16 + (lane >> 2);
        int n0 = 2 * (lane & 3);
#pragma unroll
        for (int nt = 0; nt < 5; nt++) {
            int nn = nt * 8 + n0;
            ystage[r * 41 + nn]           = acc[mt][nt][0];
            ystage[r * 41 + nn + 1]       = acc[mt][nt][1];
            ystage[(r + 8) * 41 + nn]     = acc[mt][nt][2];
            ystage[(r + 8) * 41 + nn + 1] = acc[mt][nt][3];
        }
    }
    __syncthreads();

    // per-thread row: b = tid, t = blockIdx.x (proven epilogue code)
    int t = blockIdx.x;
    int b = tid;
    const float* bs = (const float*)(smem + SM_BIAS);
    {
        float o[OSIZE];
        float y[OSIZE];
#pragma unroll
        for (int cch = 0; cch < OSIZE; cch++)
            y[cch] = ystage[tid * 41 + cch] + bs[cch];
#pragma unroll
        for (int cch = 0; cch < 4; cch++) o[cch] = 1.0f + softplus_f(y[cch]);
#pragma unroll
        for (int cch = 4; cch < 8; cch++) o[cch] = 0.1f + softplus_f(y[cch]);
        float* ewb = g_ew + (size_t)t * NTRANS * NBATCH + b;
#pragma unroll
        for (int cch = 8; cch < OSIZE; cch++) {
            float tr = 5.0f * tanhf(y[cch]);
            o[cch] = tr;                                   // logZ fixed by k3
            ewb[(size_t)(cch - 8) * NBATCH] = __expf(tr);  // coalesced STG.32
        }
        // write o back in place (each thread touches only its own row)
#pragma unroll
        for (int cch = 0; cch < OSIZE; cch++)
            ystage[tid * 41 + cch] = o[cch];
    }
    __syncthreads();
    // coalesced readout: 1280 float4 = 128 threads x 10
    float* obase = out + (size_t)t * NBATCH * OSIZE;
#pragma unroll
    for (int q = 0; q < 10; q++) {
        int g4 = q * 128 + tid;
        int g = 4 * g4;
        int rl = g / OSIZE;
        int ch = g - rl * OSIZE;
        const float* sp = ystage + rl * 41 + ch;
        ((float4*)obase)[g4] = make_float4(sp[0], sp[1], sp[2], sp[3]);
    }
}

// ---------------- CRF step in exp domain ----------------
// Transposed layout: e[ch] at g_ew[(t*32+ch)*128 + b] -> coalesced LDG.32.
__device__ __forceinline__ void loadE(float e[NTRANS], int t, int b) {
    const float* p = g_ew + (size_t)t * NTRANS * NBATCH + b;
#pragma unroll
    for (int ch = 0; ch < NTRANS; ch++) e[ch] = p[(size_t)ch * NBATCH];
}

__device__ __forceinline__ void stepf(float p[8], const float e[NTRANS]) {
    float np[8];
#pragma unroll
    for (int i = 0; i < 4; i++) {
        float m = 0.0f, s = 0.0f;
#pragma unroll
        for (int j = 0; j < 8; j++) {
            float v = p[j] * e[i * 8 + j];
            if (j == i || j == i + 4) s += v;   // "stay" terms
            else                      m += v;   // "move" terms
        }
        np[i] = m;
        np[i + 4] = s;
    }
#pragma unroll
    for (int i = 0; i < 8; i++) p[i] = np[i];
}

// ---------------- Kernel 2a: per-chunk matrices, normalized ----------------
__global__ void __launch_bounds__(128, 1) k2a_chunk()
{
    int b = threadIdx.x;           // batch
    int c = blockIdx.x;            // chunk
    int t0 = c * CHUNK;

    float M[8][8];                 // M[j] = column j
#pragma unroll
    for (int j = 0; j < 8; j++)
#pragma unroll
        for (int i = 0; i < 8; i++) M[j][i] = (i == j) ? 1.0f : 0.0f;

    float eA[NTRANS], eB[NTRANS];
    loadE(eA, t0, b);
#pragma unroll 1
    for (int s = 0; s < CHUNK; s += 2) {
        loadE(eB, t0 + s + 1, b);
#pragma unroll
        for (int j = 0; j < 8; j++) stepf(M[j], eA);
        loadE(eA, t0 + s + 2, b);   // s=8 reads pad: discarded
#pragma unroll
        for (int j = 0; j < 8; j++) stepf(M[j], eB);
    }

    // normalize by exact power of two (max entry -> [1,2))
    float maxv = 0.0f;
#pragma unroll
    for (int j = 0; j < 8; j++)
#pragma unroll
        for (int i = 0; i < 8; i++) maxv = fmaxf(maxv, M[j][i]);
    int e = (int)(__float_as_uint(maxv) >> 23) - 127;
    float scale = __uint_as_float((unsigned)(127 - e) << 23);
#pragma unroll
    for (int j = 0; j < 8; j++)
#pragma unroll
        for (int i = 0; i < 8; i++) M[j][i] *= scale;
    g_chunkE[c * NBATCH + b] = e;

    float4* dst = (float4*)g_chunkM;
#pragma unroll
    for (int j = 0; j < 8; j++) {
        dst[((size_t)c * 16 + 2 * j)     * NBATCH + b] = make_float4(M[j][0], M[j][1], M[j][2], M[j][3]);
        dst[((size_t)c * 16 + 2 * j + 1) * NBATCH + b] = make_float4(M[j][4], M[j][5], M[j][6], M[j][7]);
    }
}

// load matrix as u64 column-pairs: m[4*j+qq] = (M[j][2qq], M[j][2qq+1])
__device__ __forceinline__ void loadMp(unsigned long long m[32],
                                       const float* srcM, int c, int b) {
    const float4* p4 = (const float4*)srcM;
#pragma unroll
    for (int q = 0; q < 16; q++) {
        float4 t = p4[((size_t)c * 16 + q) * NBATCH + b];   // coalesced
        m[2 * q]     = pack2(t.x, t.y);
        m[2 * q + 1] = pack2(t.z, t.w);
    }
}

// ---------------- Kernel 2b: group products of 10 chunk matrices ------------
__global__ void __launch_bounds__(128, 1) k2b_grp()
{
    int b = threadIdx.x;
    int g = blockIdx.x;

    float G[8][8];                  // G[j] = column j
    {
        const float4* p4 = (const float4*)g_chunkM;
#pragma unroll
        for (int q = 0; q < 16; q++) {
            float4 t = p4[((size_t)(g * GRP) * 16 + q) * NBATCH + b];
            int j = q >> 1, h = (q & 1) * 4;
            G[j][h] = t.x; G[j][h + 1] = t.y; G[j][h + 2] = t.z; G[j][h + 3] = t.w;
        }
    }

#pragma unroll 1
    for (int s = 1; s < GRP; s++) {
        unsigned long long A[32];
        loadMp(A, g_chunkM, g * GRP + s, b);
#pragma unroll
        for (int j = 0; j < 8; j++) {
            unsigned long long nv[4];
#pragma unroll
            for (int qq = 0; qq < 4; qq++) nv[qq] = pack2(0.0f, 0.0f);
#pragma unroll
            for (int jj = 0; jj < 8; jj++) {
                unsigned long long vj = pack2(G[j][jj], G[j][jj]);
#pragma unroll
                for (int qq = 0; qq < 4; qq++)
                    nv[qq] = fma2(A[4 * jj + qq], vj, nv[qq]);
            }
#pragma unroll
            for (int qq = 0; qq < 4; qq++)
                unpack2(nv[qq], G[j][2 * qq], G[j][2 * qq + 1]);
        }
    }

    int esum = 0;
#pragma unroll
    for (int s = 0; s < GRP; s++) esum += g_chunkE[(g * GRP + s) * NBATCH + b];
    g_grpE[g * NBATCH + b] = esum;

    float4* dst = (float4*)g_grpM;
#pragma unroll
    for (int j = 0; j < 8; j++) {
        dst[((size_t)g * 16 + 2 * j)     * NBATCH + b] = make_float4(G[j][0], G[j][1], G[j][2], G[j][3]);
        dst[((size_t)g * 16 + 2 * j + 1) * NBATCH + b] = make_float4(G[j][4], G[j][5], G[j][6], G[j][7]);
    }
}

// ---------------- Kernel 2c: two independent 10-deep folds ------------------
__device__ __forceinline__ void foldR(const unsigned long long m[32],
                                      float v[8], int& esum) {
    unsigned long long nv[4];
#pragma unroll
    for (int qq = 0; qq < 4; qq++) nv[qq] = pack2(0.0f, 0.0f);
#pragma unroll
    for (int j = 0; j < 8; j++) {
        unsigned long long vj = pack2(v[j], v[j]);
#pragma unroll
        for (int qq = 0; qq < 4; qq++)
            nv[qq] = fma2(m[4 * j + qq], vj, nv[qq]);
    }
    unsigned long long t = add2(add2(nv[0], nv[1]), add2(nv[2], nv[3]));
    float slo, shi;
    unpack2(t, slo, shi);
    float S = slo + shi;
    int e = (int)(__float_as_uint(S) >> 23) - 127;
    float scale = __uint_as_float((unsigned)(127 - e) << 23);   // exact 2^-e
    esum += e;
    unsigned long long s2 = pack2(scale, scale);
#pragma unroll
    for (int qq = 0; qq < 4; qq++) {
        unsigned long long u = mul2(nv[qq], s2);
        unpack2(u, v[2 * qq], v[2 * qq + 1]);
    }
}

__device__ __forceinline__ void foldL(const unsigned long long m[32],
                                      float u[8], int& esum) {
    unsigned long long up[4];
#pragma unroll
    for (int qq = 0; qq < 4; qq++) up[qq] = pack2(u[2 * qq], u[2 * qq + 1]);
    float nu[8];
#pragma unroll
    for (int j = 0; j < 8; j++) {
        unsigned long long d = mul2(m[4 * j], up[0]);
#pragma unroll
        for (int qq = 1; qq < 4; qq++)
            d = fma2(m[4 * j + qq], up[qq], d);
        float lo, hi;
        unpack2(d, lo, hi);
        nu[j] = lo + hi;
    }
    float S = ((nu[0] + nu[1]) + (nu[2] + nu[3])) + ((nu[4] + nu[5]) + (nu[6] + nu[7]));
    int e = (int)(__float_as_uint(S) >> 23) - 127;
    float scale = __uint_as_float((unsigned)(127 - e) << 23);
    esum += e;
#pragma unroll
    for (int j = 0; j < 8; j++) u[j] = nu[j] * scale;
}

__global__ void __launch_bounds__(32, 1) k2c_combine()
{
    int b = blockIdx.x * 32 + threadIdx.x;

    int esum = 0;
#pragma unroll
    for (int g = 0; g < NGRP; g++) esum += g_grpE[g * NBATCH + b];

    float v[8], u[8];
#pragma unroll
    for (int i = 0; i < 8; i++) { v[i] = 1.0f; u[i] = 1.0f; }

#pragma unroll 1
    for (int s = 0; s < NGRP / 2; s++) {
        unsigned long long mV[32], mU[32];
        loadMp(mV, g_grpM, s, b);               // R chain: G_0 .. G_9
        loadMp(mU, g_grpM, NGRP - 1 - s, b);    // L chain: G_19 .. G_10
        foldR(mV, v, esum);
        foldL(mU, u, esum);
    }

    float S = 0.0f;
#pragma unroll
    for (int i = 0; i < 8; i++) S = fmaf(u[i], v[i], S);
    double lz = ((double)esum * 0.69314718055994530942 + log((double)S))
                / (double)NTIME;
    g_logZ[b] = (float)lz;
}

// ---------------- Kernel 3: out[..., 8:40] -= logZ[b] ----------------
__global__ void __launch_bounds__(256) k3_fixup(float* __restrict__ out)
{
    int q = blockIdx.x * 256 + threadIdx.x;      // one float4 of 32 trans channels
    if (q >= NTIME * NBATCH * 8) return;
    int tb = q >> 3;
    int sub = q & 7;
    float lz = g_logZ[tb & (NBATCH - 1)];
    float4* ptr = (float4*)(out + (size_t)tb * OSIZE + 8) + sub;
    float4 v = *ptr;
    v.x -= lz; v.y -= lz; v.z -= lz; v.w -= lz;
    *ptr = v;
}

extern "C" void kernel_launch(void* const* d_in, const int* in_sizes, int n_in,
                              void* d_out, int out_size)
{
    const float* x = (const float*)d_in[0];
    const float* W = (const float*)d_in[1];
    const float* b = (const float*)d_in[2];
    float* out = (float*)d_out;

    static int smem_set = 0;
    if (!smem_set) {
        cudaFuncSetAttribute(k1_gemm_mma,
                             cudaFuncAttributeMaxDynamicSharedMemorySize, K1_SMEM);
        smem_set = 1;
    }

    k1_gemm_mma<<<NTIME, 128, K1_SMEM>>>(x, W, b, out);
    k2a_chunk<<<NCHUNK, 128>>>();
    k2b_grp<<<NGRP, 128>>>();
    k2c_combine<<<NBATCH / 32, 32>>>();
    k3_fixup<<<(NTIME * NBATCH * 8 + 255) / 256, 256>>>(out);
}